// round 11
// baseline (speedup 1.0000x reference)
#include <cuda_runtime.h>
#include <cuda_fp16.h>
#include <cstdint>

// ConvDemodulated: out[b,o,hw] = clip( sum_i x[b,i,hw] * Wn[o,i] + bias[o], -256, 256 )
// R8 = R4 (best, 88.6us wall / 79.5us kernel) with the weight-prep kernel FUSED:
// each CTA redundantly normalizes+packs W from L2-hot gmem (16KB) in its prologue,
// overlapped with the x staging loads already in flight. Single kernel launch.
// R4's load structure (16 front-batched LDG.128, 4 CTAs/SM) is untouched — R6/R7
// proved DRAM duty is set by CTAs/SM x batched-LDG, and 4x16 is the sweet spot.

#define CIN   64
#define COUT  64
#define HWSZ  65536
#define PTILE 128      // pixels per CTA
#define S2U   132      // staging stride (uint2), mod 16 == 4 -> conflict-free LDS.64
#define SEF   136      // epilogue stride (floats)
#define WNS   72       // raw-W smem row stride (floats): frag LDS.64 -> 2-way max

#define SMEM_WN_B  (COUT * WNS * 4)          // 18432 B raw W
#define SMEM_SE_B  (COUT * SEF * 4)          // 34816 B staging/epilogue union
#define SMEM_TOTAL (SMEM_WN_B + SMEM_SE_B)   // 53248 B -> 4 CTAs/SM

__device__ __forceinline__ uint32_t pack_h2(float lo, float hi) {
    __half2 h = __floats2half2_rn(lo, hi);
    return *reinterpret_cast<uint32_t*>(&h);
}

__global__ void __launch_bounds__(128, 4)
conv_mma_kernel(const float* __restrict__ x, const float* __restrict__ w,
                const float* __restrict__ bias, float* __restrict__ out) {
    extern __shared__ __align__(16) char dsm[];
    float* WN = (float*)dsm;                   // [64][WNS] raw weights
    float* SE = (float*)(dsm + SMEM_WN_B);     // staging (as uint2) then epilogue
    uint2* SB = (uint2*)SE;
    __shared__ float dcoef[COUT];

    const int tid  = threadIdx.x;
    const int lane = tid & 31;
    const int wid  = tid >> 5;     // 0..3
    const int cw   = wid & 1;      // cout half
    const int ph   = wid >> 1;     // pixel half
    const int t    = lane & 3;
    const int g    = lane >> 2;
    const int pixb = ph * 64;

    const int pixglob = blockIdx.x * PTILE;
    const int b   = pixglob >> 16;
    const int hw0 = pixglob & (HWSZ - 1);
    const float* xb = x + ((size_t)b << 22) + hw0;

    // ---- stage X first: 16 front-batched LDG.128 hit DRAM immediately (R4 layout) ----
#pragma unroll
    for (int it = 0; it < 4; it++) {
        const int q  = it * 4 + wid;                 // 0..15
        const int k0 = it * 16 + wid * 2;
        const float* rp = xb + ((size_t)k0 << 16) + lane * 4;
        float4 va = __ldcs((const float4*)rp);
        float4 vb = __ldcs((const float4*)(rp + (1 << 16)));
        float4 vc = __ldcs((const float4*)(rp + (8 << 16)));
        float4 vd = __ldcs((const float4*)(rp + (9 << 16)));
        uint4 o0, o1;
        o0.x = pack_h2(va.x, vb.x); o0.y = pack_h2(vc.x, vd.x);
        o0.z = pack_h2(va.y, vb.y); o0.w = pack_h2(vc.y, vd.y);
        o1.x = pack_h2(va.z, vb.z); o1.y = pack_h2(vc.z, vd.z);
        o1.z = pack_h2(va.w, vb.w); o1.w = pack_h2(vc.w, vd.w);
        *(uint4*)&SB[q * S2U + lane * 4]     = o0;
        *(uint4*)&SB[q * S2U + lane * 4 + 2] = o1;
    }

    // ---- load raw W -> WN (L2-hot 16KB; latency hides under the x loads above) ----
#pragma unroll
    for (int i = 0; i < 8; i++) {
        const int idx = i * 128 + tid;      // float4 index, 1024 total
        const int row = idx >> 4;
        const int c4  = idx & 15;
        float4 v = __ldg((const float4*)w + idx);
        *(float4*)&WN[row * WNS + c4 * 4] = v;
    }
    __syncthreads();

    // ---- row norms: 2 threads per row, shfl combine ----
    {
        const int row  = tid >> 1;
        const int half = tid & 1;
        const float* rw = &WN[row * WNS + half * 32];
        float s0 = 0.f, s1 = 0.f, s2 = 0.f, s3 = 0.f;
#pragma unroll
        for (int i = 0; i < 8; i++) {
            float4 v = *(const float4*)(rw + i * 4);
            s0 += v.x * v.x; s1 += v.y * v.y;
            s2 += v.z * v.z; s3 += v.w * v.w;
        }
        float s = (s0 + s1) + (s2 + s3);
        s += __shfl_xor_sync(0xFFFFFFFFu, s, 1);
        if (half == 0) dcoef[row] = rsqrtf(s + 1e-8f);
    }
    __syncthreads();

    // ---- pack A fragments (m16n8k16 row-major) from WN * dcoef ----
    uint4 aw[2][4];
#pragma unroll
    for (int m = 0; m < 2; m++) {
        const int r = cw * 32 + m * 16 + g;
        const float d0 = dcoef[r];
        const float d1 = dcoef[r + 8];
#pragma unroll
        for (int kb = 0; kb < 4; kb++) {
            const int c = kb * 16 + 2 * t;
            float2 p0 = *(const float2*)&WN[r * WNS + c];
            float2 p1 = *(const float2*)&WN[(r + 8) * WNS + c];
            float2 p2 = *(const float2*)&WN[r * WNS + c + 8];
            float2 p3 = *(const float2*)&WN[(r + 8) * WNS + c + 8];
            aw[m][kb].x = pack_h2(d0 * p0.x, d0 * p0.y);
            aw[m][kb].y = pack_h2(d1 * p1.x, d1 * p1.y);
            aw[m][kb].z = pack_h2(d0 * p2.x, d0 * p2.y);
            aw[m][kb].w = pack_h2(d1 * p3.x, d1 * p3.y);
        }
    }

    float acc[2][8][4];
#pragma unroll
    for (int m = 0; m < 2; m++)
#pragma unroll
        for (int nt = 0; nt < 8; nt++)
#pragma unroll
            for (int j = 0; j < 4; j++) acc[m][nt][j] = 0.0f;

    // ---- mainloop: 4 k-blocks x 8 n-tiles x 2 m-tiles of m16n8k16 (R4 exact) ----
#pragma unroll
    for (int kb = 0; kb < 4; kb++) {
#pragma unroll
        for (int nt = 0; nt < 8; nt++) {
            const uint2 bb = SB[(kb * 4 + t) * S2U + pixb + nt * 8 + g];
            asm volatile(
                "mma.sync.aligned.m16n8k16.row.col.f32.f16.f16.f32 "
                "{%0,%1,%2,%3}, {%4,%5,%6,%7}, {%8,%9}, {%0,%1,%2,%3};"
                : "+f"(acc[0][nt][0]), "+f"(acc[0][nt][1]),
                  "+f"(acc[0][nt][2]), "+f"(acc[0][nt][3])
                : "r"(aw[0][kb].x), "r"(aw[0][kb].y),
                  "r"(aw[0][kb].z), "r"(aw[0][kb].w),
                  "r"(bb.x), "r"(bb.y));
            asm volatile(
                "mma.sync.aligned.m16n8k16.row.col.f32.f16.f16.f32 "
                "{%0,%1,%2,%3}, {%4,%5,%6,%7}, {%8,%9}, {%0,%1,%2,%3};"
                : "+f"(acc[1][nt][0]), "+f"(acc[1][nt][1]),
                  "+f"(acc[1][nt][2]), "+f"(acc[1][nt][3])
                : "r"(aw[1][kb].x), "r"(aw[1][kb].y),
                  "r"(aw[1][kb].z), "r"(aw[1][kb].w),
                  "r"(bb.x), "r"(bb.y));
        }
    }

    __syncthreads();   // mainloop SB reads done before union overwrite

    // ---- epilogue pt1: bias+clamp, STS into [cout][pix] ----
#pragma unroll
    for (int m = 0; m < 2; m++) {
        const int row0 = cw * 32 + m * 16 + g;
        const float bv0 = __ldg(bias + row0);
        const float bv1 = __ldg(bias + row0 + 8);
#pragma unroll
        for (int nt = 0; nt < 8; nt++) {
            const int col = pixb + nt * 8 + t * 2;
            float2 v0, v1;
            v0.x = fminf(fmaxf(acc[m][nt][0] + bv0, -256.0f), 256.0f);
            v0.y = fminf(fmaxf(acc[m][nt][1] + bv0, -256.0f), 256.0f);
            v1.x = fminf(fmaxf(acc[m][nt][2] + bv1, -256.0f), 256.0f);
            v1.y = fminf(fmaxf(acc[m][nt][3] + bv1, -256.0f), 256.0f);
            *(float2*)&SE[row0 * SEF + col]       = v0;
            *(float2*)&SE[(row0 + 8) * SEF + col] = v1;
        }
    }
    __syncthreads();

    // ---- epilogue pt2: coalesced 512B-per-warp copy out ----
    float* ob = out + ((size_t)b << 22) + hw0;
#pragma unroll
    for (int p = 0; p < 16; p++) {
        const int row = p * 4 + wid;               // cout
        float4 v = *(const float4*)&SE[row * SEF + lane * 4];
        __stcs((float4*)(ob + ((size_t)row << 16) + lane * 4), v);
    }
}

// ---------------- launch: ONE kernel, no prep ----------------
extern "C" void kernel_launch(void* const* d_in, const int* in_sizes, int n_in,
                              void* d_out, int out_size) {
    const float* x    = (const float*)d_in[0];
    const float* w    = (const float*)d_in[1];
    const float* bias = (const float*)d_in[2];
    float* out = (float*)d_out;

    // Unconditional (deterministic, no static guards); not a stream op, capture-safe.
    cudaFuncSetAttribute(conv_mma_kernel,
                         cudaFuncAttributeMaxDynamicSharedMemorySize, SMEM_TOTAL);

    const int total_pix = 16 * HWSZ;
    const int nblocks = total_pix / PTILE;   // 8192
    conv_mma_kernel<<<nblocks, 128, SMEM_TOTAL>>>(x, w, bias, out);
}

// round 12
// speedup vs baseline: 1.0305x; 1.0305x over previous
#include <cuda_runtime.h>
#include <cuda_fp16.h>
#include <cstdint>

// ConvDemodulated: out[b,o,hw] = clip( sum_i x[b,i,hw] * Wn[o,i] + bias[o], -256, 256 )
// R9 = R4 (best 88.6us wall / 79.5us kernel) + SYNC-FREE fused weight prep:
// per-warp norm computation via gmem LDG (L1-hot, 16KB) + shfl_xor within the
// 4-lane t-quads; fragments packed straight from gmem. No extra smem (L1
// carveout preserved), no extra __syncthreads (R8's fatal flaws). One launch.

#define CIN   64
#define COUT  64
#define HWSZ  65536
#define PTILE 128      // pixels per CTA
#define S2U   132      // staging stride (uint2), mod 16 == 4 -> conflict-free LDS.64
#define SEF   136      // epilogue stride (floats)

__device__ __forceinline__ uint32_t pack_h2(float lo, float hi) {
    __half2 h = __floats2half2_rn(lo, hi);
    return *reinterpret_cast<uint32_t*>(&h);
}

__global__ void __launch_bounds__(128, 4)
conv_mma_kernel(const float* __restrict__ x, const float* __restrict__ w,
                const float* __restrict__ bias, float* __restrict__ out) {
    // Union: staging (16 quad-rows x 132 uint2 = 16.9KB) then epilogue (64 x 136 fp32)
    __shared__ __align__(16) float SE[COUT * SEF];
    uint2* SB = (uint2*)SE;

    const int tid  = threadIdx.x;
    const int lane = tid & 31;
    const int wid  = tid >> 5;     // 0..3
    const int cw   = wid & 1;      // cout half
    const int ph   = wid >> 1;     // pixel half
    const int t    = lane & 3;
    const int g    = lane >> 2;
    const int pixb = ph * 64;

    const int pixglob = blockIdx.x * PTILE;
    const int b   = pixglob >> 16;
    const int hw0 = pixglob & (HWSZ - 1);
    const float* xb = x + ((size_t)b << 22) + hw0;

    // ---- stage X first: 16 front-batched LDG.128 hit DRAM immediately (R4 exact) ----
#pragma unroll
    for (int it = 0; it < 4; it++) {
        const int q  = it * 4 + wid;                 // 0..15
        const int k0 = it * 16 + wid * 2;
        const float* rp = xb + ((size_t)k0 << 16) + lane * 4;
        float4 va = __ldcs((const float4*)rp);
        float4 vb = __ldcs((const float4*)(rp + (1 << 16)));
        float4 vc = __ldcs((const float4*)(rp + (8 << 16)));
        float4 vd = __ldcs((const float4*)(rp + (9 << 16)));
        uint4 o0, o1;
        o0.x = pack_h2(va.x, vb.x); o0.y = pack_h2(vc.x, vd.x);
        o0.z = pack_h2(va.y, vb.y); o0.w = pack_h2(vc.y, vd.y);
        o1.x = pack_h2(va.z, vb.z); o1.y = pack_h2(vc.z, vd.z);
        o1.z = pack_h2(va.w, vb.w); o1.w = pack_h2(vc.w, vd.w);
        *(uint4*)&SB[q * S2U + lane * 4]     = o0;
        *(uint4*)&SB[q * S2U + lane * 4 + 2] = o1;
    }

    // ---- per-warp weight prep (no smem, no syncs; w is 16KB -> L1-hot) ----
    // Rows this thread's fragments need: r0, r0+8 (m=0), r0+16, r0+24 (m=1).
    const int r0 = cw * 32 + g;
    float dcoef[4];
    {
        // The 4 lanes sharing g split each row's 64 cols: lane t sums [16t,16t+16).
#pragma unroll
        for (int rr = 0; rr < 4; rr++) {
            const float* rw = w + (size_t)(r0 + rr * 8) * CIN + t * 16;
            float4 v0 = __ldg((const float4*)rw);
            float4 v1 = __ldg((const float4*)rw + 1);
            float4 v2 = __ldg((const float4*)rw + 2);
            float4 v3 = __ldg((const float4*)rw + 3);
            float s = v0.x*v0.x + v0.y*v0.y + v0.z*v0.z + v0.w*v0.w
                    + v1.x*v1.x + v1.y*v1.y + v1.z*v1.z + v1.w*v1.w
                    + v2.x*v2.x + v2.y*v2.y + v2.z*v2.z + v2.w*v2.w
                    + v3.x*v3.x + v3.y*v3.y + v3.z*v3.z + v3.w*v3.w;
            s += __shfl_xor_sync(0xFFFFFFFFu, s, 1);
            s += __shfl_xor_sync(0xFFFFFFFFu, s, 2);
            dcoef[rr] = rsqrtf(s + 1e-8f);
        }
    }

    // ---- pack A fragments (m16n8k16 row-major) straight from gmem (L1-hot) ----
    uint4 aw[2][4];
#pragma unroll
    for (int m = 0; m < 2; m++) {
        const int r = r0 + m * 16;
        const float d0 = dcoef[m * 2];
        const float d1 = dcoef[m * 2 + 1];
#pragma unroll
        for (int kb = 0; kb < 4; kb++) {
            const int c = kb * 16 + 2 * t;
            float2 p0 = __ldg((const float2*)(w + (size_t)r * CIN + c));
            float2 p1 = __ldg((const float2*)(w + (size_t)(r + 8) * CIN + c));
            float2 p2 = __ldg((const float2*)(w + (size_t)r * CIN + c + 8));
            float2 p3 = __ldg((const float2*)(w + (size_t)(r + 8) * CIN + c + 8));
            aw[m][kb].x = pack_h2(d0 * p0.x, d0 * p0.y);
            aw[m][kb].y = pack_h2(d1 * p1.x, d1 * p1.y);
            aw[m][kb].z = pack_h2(d0 * p2.x, d0 * p2.y);
            aw[m][kb].w = pack_h2(d1 * p3.x, d1 * p3.y);
        }
    }

    float acc[2][8][4];
#pragma unroll
    for (int m = 0; m < 2; m++)
#pragma unroll
        for (int nt = 0; nt < 8; nt++)
#pragma unroll
            for (int j = 0; j < 4; j++) acc[m][nt][j] = 0.0f;

    __syncthreads();   // staging STS visible (the ONE barrier, same as R4)

    // ---- mainloop: 4 k-blocks x 8 n-tiles x 2 m-tiles of m16n8k16 (R4 exact) ----
#pragma unroll
    for (int kb = 0; kb < 4; kb++) {
#pragma unroll
        for (int nt = 0; nt < 8; nt++) {
            const uint2 bb = SB[(kb * 4 + t) * S2U + pixb + nt * 8 + g];
            asm volatile(
                "mma.sync.aligned.m16n8k16.row.col.f32.f16.f16.f32 "
                "{%0,%1,%2,%3}, {%4,%5,%6,%7}, {%8,%9}, {%0,%1,%2,%3};"
                : "+f"(acc[0][nt][0]), "+f"(acc[0][nt][1]),
                  "+f"(acc[0][nt][2]), "+f"(acc[0][nt][3])
                : "r"(aw[0][kb].x), "r"(aw[0][kb].y),
                  "r"(aw[0][kb].z), "r"(aw[0][kb].w),
                  "r"(bb.x), "r"(bb.y));
            asm volatile(
                "mma.sync.aligned.m16n8k16.row.col.f32.f16.f16.f32 "
                "{%0,%1,%2,%3}, {%4,%5,%6,%7}, {%8,%9}, {%0,%1,%2,%3};"
                : "+f"(acc[1][nt][0]), "+f"(acc[1][nt][1]),
                  "+f"(acc[1][nt][2]), "+f"(acc[1][nt][3])
                : "r"(aw[1][kb].x), "r"(aw[1][kb].y),
                  "r"(aw[1][kb].z), "r"(aw[1][kb].w),
                  "r"(bb.x), "r"(bb.y));
        }
    }

    __syncthreads();   // mainloop SB reads done before union overwrite

    // ---- epilogue pt1: bias+clamp, STS into [cout][pix] (R4 exact) ----
#pragma unroll
    for (int m = 0; m < 2; m++) {
        const int row0 = cw * 32 + m * 16 + g;
        const float bv0 = __ldg(bias + row0);
        const float bv1 = __ldg(bias + row0 + 8);
#pragma unroll
        for (int nt = 0; nt < 8; nt++) {
            const int col = pixb + nt * 8 + t * 2;
            float2 v0, v1;
            v0.x = fminf(fmaxf(acc[m][nt][0] + bv0, -256.0f), 256.0f);
            v0.y = fminf(fmaxf(acc[m][nt][1] + bv0, -256.0f), 256.0f);
            v1.x = fminf(fmaxf(acc[m][nt][2] + bv1, -256.0f), 256.0f);
            v1.y = fminf(fmaxf(acc[m][nt][3] + bv1, -256.0f), 256.0f);
            *(float2*)&SE[row0 * SEF + col]       = v0;
            *(float2*)&SE[(row0 + 8) * SEF + col] = v1;
        }
    }
    __syncthreads();

    // ---- epilogue pt2: coalesced 512B-per-warp copy out (R4 exact) ----
    float* ob = out + ((size_t)b << 22) + hw0;
#pragma unroll
    for (int p = 0; p < 16; p++) {
        const int row = p * 4 + wid;               // cout
        float4 v = *(const float4*)&SE[row * SEF + lane * 4];
        __stcs((float4*)(ob + ((size_t)row << 16) + lane * 4), v);
    }
}

// ---------------- launch: ONE kernel, no prep ----------------
extern "C" void kernel_launch(void* const* d_in, const int* in_sizes, int n_in,
                              void* d_out, int out_size) {
    const float* x    = (const float*)d_in[0];
    const float* w    = (const float*)d_in[1];
    const float* bias = (const float*)d_in[2];
    float* out = (float*)d_out;

    const int total_pix = 16 * HWSZ;
    const int nblocks = total_pix / PTILE;   // 8192
    conv_mma_kernel<<<nblocks, 128>>>(x, w, bias, out);
}

// round 15
// speedup vs baseline: 1.2359x; 1.1993x over previous
#include <cuda_runtime.h>
#include <cuda_fp16.h>
#include <cstdint>

// ConvDemodulated: out[b,o,hw] = clip( sum_i x[b,i,hw] * Wn[o,i] + bias[o], -256, 256 )
// R11 = R10 with the WN alignment bug fixed (WNS 66 -> 68; float4 accesses at
// row*WNS must be 16B aligned). Otherwise identical:
//  - R4 mainloop/epilogue (best kernel: 79.5us)
//  - fused weight prep: coalesced LDG.128 w -> dead upper half of SE union,
//    norms+packing via LDS, zero extra smem, zero extra syncs, ONE launch.

#define CIN   64
#define COUT  64
#define HWSZ  65536
#define PTILE 128      // pixels per CTA
#define S2U   132      // staging stride (uint2), mod 16 == 4 -> conflict-free LDS.64
#define SEF   136      // epilogue stride (floats)
#define WNS   68       // WN stride (floats): multiple of 4 -> float4 aligned

// SE float layout: [0 .. 4224)       = SB staging (16*132 uint2 = 16896B)
//                  [4224 .. 8576)    = WN raw weights (64 x 68 = 17408B)
//                  whole buffer reused as epilogue [cout][SEF] after mainloop.
#define WN_OFF 4224

__device__ __forceinline__ uint32_t pack_h2(float lo, float hi) {
    __half2 h = __floats2half2_rn(lo, hi);
    return *reinterpret_cast<uint32_t*>(&h);
}

__global__ void __launch_bounds__(128, 4)
conv_mma_kernel(const float* __restrict__ x, const float* __restrict__ w,
                const float* __restrict__ bias, float* __restrict__ out) {
    __shared__ __align__(16) float SE[COUT * SEF];   // 34816 B (same as R4)
    uint2* SB = (uint2*)SE;
    float* WN = SE + WN_OFF;

    const int tid  = threadIdx.x;
    const int lane = tid & 31;
    const int wid  = tid >> 5;     // 0..3
    const int cw   = wid & 1;      // cout half
    const int ph   = wid >> 1;     // pixel half
    const int t    = lane & 3;
    const int g    = lane >> 2;
    const int pixb = ph * 64;

    const int pixglob = blockIdx.x * PTILE;
    const int b   = pixglob >> 16;
    const int hw0 = pixglob & (HWSZ - 1);
    const float* xb = x + ((size_t)b << 22) + hw0;

    // ---- stage X first: 16 front-batched LDG.128 hit DRAM immediately (R4 exact) ----
#pragma unroll
    for (int it = 0; it < 4; it++) {
        const int q  = it * 4 + wid;                 // 0..15
        const int k0 = it * 16 + wid * 2;
        const float* rp = xb + ((size_t)k0 << 16) + lane * 4;
        float4 va = __ldcs((const float4*)rp);
        float4 vb = __ldcs((const float4*)(rp + (1 << 16)));
        float4 vc = __ldcs((const float4*)(rp + (8 << 16)));
        float4 vd = __ldcs((const float4*)(rp + (9 << 16)));
        uint4 o0, o1;
        o0.x = pack_h2(va.x, vb.x); o0.y = pack_h2(vc.x, vd.x);
        o0.z = pack_h2(va.y, vb.y); o0.w = pack_h2(vc.y, vd.y);
        o1.x = pack_h2(va.z, vb.z); o1.y = pack_h2(vc.z, vd.z);
        o1.z = pack_h2(va.w, vb.w); o1.w = pack_h2(vc.w, vd.w);
        *(uint4*)&SB[q * S2U + lane * 4]     = o0;
        *(uint4*)&SB[q * S2U + lane * 4 + 2] = o1;
    }

    // ---- load raw W coalesced -> WN (8 contiguous LDG.128/thread; L2-hot 16KB) ----
#pragma unroll
    for (int i = 0; i < 8; i++) {
        const int idx = i * 128 + tid;      // float4 index, 1024 total, contiguous
        const int row = idx >> 4;
        const int c4  = idx & 15;
        float4 v = __ldg((const float4*)w + idx);
        *(float4*)&WN[row * WNS + c4 * 4] = v;   // row*68 is multiple of 4 -> 16B aligned
    }

    __syncthreads();   // the ONE pre-mainloop barrier (covers SB staging AND WN)

    // ---- norms from smem: t-quad lanes split cols, shfl combine ----
    const int r0 = cw * 32 + g;
    float dcoef[4];
#pragma unroll
    for (int rr = 0; rr < 4; rr++) {
        const float* rw = &WN[(r0 + rr * 8) * WNS + t * 16];
        float4 v0 = *(const float4*)(rw);
        float4 v1 = *(const float4*)(rw + 4);
        float4 v2 = *(const float4*)(rw + 8);
        float4 v3 = *(const float4*)(rw + 12);
        float s = v0.x*v0.x + v0.y*v0.y + v0.z*v0.z + v0.w*v0.w
                + v1.x*v1.x + v1.y*v1.y + v1.z*v1.z + v1.w*v1.w
                + v2.x*v2.x + v2.y*v2.y + v2.z*v2.z + v2.w*v2.w
                + v3.x*v3.x + v3.y*v3.y + v3.z*v3.z + v3.w*v3.w;
        s += __shfl_xor_sync(0xFFFFFFFFu, s, 1);
        s += __shfl_xor_sync(0xFFFFFFFFu, s, 2);
        dcoef[rr] = rsqrtf(s + 1e-8f);
    }

    // ---- pack A fragments (m16n8k16 row-major) from WN smem ----
    uint4 aw[2][4];
#pragma unroll
    for (int m = 0; m < 2; m++) {
        const int r = r0 + m * 16;
        const float d0 = dcoef[m * 2];
        const float d1 = dcoef[m * 2 + 1];
#pragma unroll
        for (int kb = 0; kb < 4; kb++) {
            const int c = kb * 16 + 2 * t;
            float2 p0 = *(const float2*)&WN[r * WNS + c];
            float2 p1 = *(const float2*)&WN[(r + 8) * WNS + c];
            float2 p2 = *(const float2*)&WN[r * WNS + c + 8];
            float2 p3 = *(const float2*)&WN[(r + 8) * WNS + c + 8];
            aw[m][kb].x = pack_h2(d0 * p0.x, d0 * p0.y);
            aw[m][kb].y = pack_h2(d1 * p1.x, d1 * p1.y);
            aw[m][kb].z = pack_h2(d0 * p2.x, d0 * p2.y);
            aw[m][kb].w = pack_h2(d1 * p3.x, d1 * p3.y);
        }
    }

    float acc[2][8][4];
#pragma unroll
    for (int m = 0; m < 2; m++)
#pragma unroll
        for (int nt = 0; nt < 8; nt++)
#pragma unroll
            for (int j = 0; j < 4; j++) acc[m][nt][j] = 0.0f;

    // ---- mainloop: 4 k-blocks x 8 n-tiles x 2 m-tiles of m16n8k16 (R4 exact) ----
#pragma unroll
    for (int kb = 0; kb < 4; kb++) {
#pragma unroll
        for (int nt = 0; nt < 8; nt++) {
            const uint2 bb = SB[(kb * 4 + t) * S2U + pixb + nt * 8 + g];
            asm volatile(
                "mma.sync.aligned.m16n8k16.row.col.f32.f16.f16.f32 "
                "{%0,%1,%2,%3}, {%4,%5,%6,%7}, {%8,%9}, {%0,%1,%2,%3};"
                : "+f"(acc[0][nt][0]), "+f"(acc[0][nt][1]),
                  "+f"(acc[0][nt][2]), "+f"(acc[0][nt][3])
                : "r"(aw[0][kb].x), "r"(aw[0][kb].y),
                  "r"(aw[0][kb].z), "r"(aw[0][kb].w),
                  "r"(bb.x), "r"(bb.y));
            asm volatile(
                "mma.sync.aligned.m16n8k16.row.col.f32.f16.f16.f32 "
                "{%0,%1,%2,%3}, {%4,%5,%6,%7}, {%8,%9}, {%0,%1,%2,%3};"
                : "+f"(acc[1][nt][0]), "+f"(acc[1][nt][1]),
                  "+f"(acc[1][nt][2]), "+f"(acc[1][nt][3])
                : "r"(aw[1][kb].x), "r"(aw[1][kb].y),
                  "r"(aw[1][kb].z), "r"(aw[1][kb].w),
                  "r"(bb.x), "r"(bb.y));
        }
    }

    __syncthreads();   // mainloop SB + WN reads done before union overwrite

    // ---- epilogue pt1: bias+clamp, STS into [cout][pix] (R4 exact) ----
#pragma unroll
    for (int m = 0; m < 2; m++) {
        const int row0 = cw * 32 + m * 16 + g;
        const float bv0 = __ldg(bias + row0);
        const float bv1 = __ldg(bias + row0 + 8);
#pragma unroll
        for (int nt = 0; nt < 8; nt++) {
            const int col = pixb + nt * 8 + t * 2;
            float2 v0, v1;
            v0.x = fminf(fmaxf(acc[m][nt][0] + bv0, -256.0f), 256.0f);
            v0.y = fminf(fmaxf(acc[m][nt][1] + bv0, -256.0f), 256.0f);
            v1.x = fminf(fmaxf(acc[m][nt][2] + bv1, -256.0f), 256.0f);
            v1.y = fminf(fmaxf(acc[m][nt][3] + bv1, -256.0f), 256.0f);
            *(float2*)&SE[row0 * SEF + col]       = v0;
            *(float2*)&SE[(row0 + 8) * SEF + col] = v1;
        }
    }
    __syncthreads();

    // ---- epilogue pt2: coalesced 512B-per-warp copy out (R4 exact) ----
    float* ob = out + ((size_t)b << 22) + hw0;
#pragma unroll
    for (int p = 0; p < 16; p++) {
        const int row = p * 4 + wid;               // cout
        float4 v = *(const float4*)&SE[row * SEF + lane * 4];
        __stcs((float4*)(ob + ((size_t)row << 16) + lane * 4), v);
    }
}

// ---------------- launch: ONE kernel, no prep ----------------
extern "C" void kernel_launch(void* const* d_in, const int* in_sizes, int n_in,
                              void* d_out, int out_size) {
    const float* x    = (const float*)d_in[0];
    const float* w    = (const float*)d_in[1];
    const float* bias = (const float*)d_in[2];
    float* out = (float*)d_out;

    const int total_pix = 16 * HWSZ;
    const int nblocks = total_pix / PTILE;   // 8192
    conv_mma_kernel<<<nblocks, 128>>>(x, w, bias, out);
}

// round 16
// speedup vs baseline: 1.4403x; 1.1654x over previous
#include <cuda_runtime.h>
#include <cuda_fp16.h>
#include <cstdint>

// ConvDemodulated: out[b,o,hw] = clip( sum_i x[b,i,hw] * Wn[o,i] + bias[o], -256, 256 )
// R12: single launch. Key idea: demodulation is a per-output-row SCALAR, so use
// RAW fp16 weights in the mma and fold dcoef[o] into the epilogue (fmaf).
//  - raw w: coalesced 8xLDG.128 -> fp16 swizzled smem tile (dead SE space)
//  - A-frags via ldmatrix.x4 (exact m16n8k16 layout, no scattered LDS)
//  - norms: square-accumulate in regs during the same sweep, shfl-tree, 256B smem
//  - zero extra smem footprint, zero extra barriers vs R4's mainloop/epilogue.

#define CIN   64
#define COUT  64
#define HWSZ  65536
#define PTILE 128      // pixels per CTA
#define S2U   132      // staging stride (uint2), mod 16 == 4 -> conflict-free LDS.64
#define SEF   136      // epilogue stride (floats)

// SE float layout: [0 .. 4224)    = SB staging (16*132 uint2 = 16896B)
//                  [4224 .. 6272) = WH raw fp16 weights (64 rows x 128B, swizzled)
//                  whole buffer reused as epilogue [cout][SEF] after mainloop.
#define WH_OFF 4224

__device__ __forceinline__ uint32_t pack_h2(float lo, float hi) {
    __half2 h = __floats2half2_rn(lo, hi);
    return *reinterpret_cast<uint32_t*>(&h);
}

__global__ void __launch_bounds__(128, 4)
conv_mma_kernel(const float* __restrict__ x, const float* __restrict__ w,
                const float* __restrict__ bias, float* __restrict__ out) {
    __shared__ __align__(16) float SE[COUT * SEF];   // 34816 B (same as R4)
    __shared__ float sdc[COUT];                       // 256 B dcoef
    uint2* SB = (uint2*)SE;
    char*  WH = (char*)(SE + WH_OFF);                 // fp16 w tile, 128B/row

    const int tid  = threadIdx.x;
    const int lane = tid & 31;
    const int wid  = tid >> 5;     // 0..3
    const int cw   = wid & 1;      // cout half
    const int ph   = wid >> 1;     // pixel half
    const int t    = lane & 3;
    const int g    = lane >> 2;
    const int pixb = ph * 64;

    const int pixglob = blockIdx.x * PTILE;
    const int b   = pixglob >> 16;
    const int hw0 = pixglob & (HWSZ - 1);
    const float* xb = x + ((size_t)b << 22) + hw0;

    // ---- stage X first: 16 front-batched LDG.128 hit DRAM immediately (R4 exact) ----
#pragma unroll
    for (int it = 0; it < 4; it++) {
        const int q  = it * 4 + wid;                 // 0..15
        const int k0 = it * 16 + wid * 2;
        const float* rp = xb + ((size_t)k0 << 16) + lane * 4;
        float4 va = __ldcs((const float4*)rp);
        float4 vb = __ldcs((const float4*)(rp + (1 << 16)));
        float4 vc = __ldcs((const float4*)(rp + (8 << 16)));
        float4 vd = __ldcs((const float4*)(rp + (9 << 16)));
        uint4 o0, o1;
        o0.x = pack_h2(va.x, vb.x); o0.y = pack_h2(vc.x, vd.x);
        o0.z = pack_h2(va.y, vb.y); o0.w = pack_h2(vc.y, vd.y);
        o1.x = pack_h2(va.z, vb.z); o1.y = pack_h2(vc.z, vd.z);
        o1.z = pack_h2(va.w, vb.w); o1.w = pack_h2(vc.w, vd.w);
        *(uint4*)&SB[q * S2U + lane * 4]     = o0;
        *(uint4*)&SB[q * S2U + lane * 4 + 2] = o1;
    }

    // ---- coalesced raw-w sweep: fp16 pack -> WH (swizzled) + norm partials in regs ----
    // idx = i*128+tid covers row = 8i + tid/16, cols [4*(tid&15), +4)
    float ps[8];
#pragma unroll
    for (int i = 0; i < 8; i++) {
        const int idx = i * 128 + tid;
        const int row = idx >> 4;
        const int c4  = idx & 15;
        float4 v = __ldg((const float4*)w + idx);
        ps[i] = v.x * v.x + v.y * v.y + v.z * v.z + v.w * v.w;
        const int phys = (c4 >> 1) ^ (row & 7);      // 16B-chunk XOR swizzle
        uint2 hv;
        hv.x = pack_h2(v.x, v.y);
        hv.y = pack_h2(v.z, v.w);
        *(uint2*)(WH + row * 128 + phys * 16 + (c4 & 1) * 8) = hv;
    }
    // reduce across the 16 lanes sharing each row-group
#pragma unroll
    for (int i = 0; i < 8; i++) {
        ps[i] += __shfl_xor_sync(0xFFFFFFFFu, ps[i], 1);
        ps[i] += __shfl_xor_sync(0xFFFFFFFFu, ps[i], 2);
        ps[i] += __shfl_xor_sync(0xFFFFFFFFu, ps[i], 4);
        ps[i] += __shfl_xor_sync(0xFFFFFFFFu, ps[i], 8);
    }
    if ((tid & 15) == 0) {
        const int j = tid >> 4;
#pragma unroll
        for (int i = 0; i < 8; i++)
            sdc[i * 8 + j] = rsqrtf(ps[i] + 1e-8f);
    }

    __syncthreads();   // the ONE pre-mainloop barrier (SB staging + WH + sdc)

    // ---- A fragments via ldmatrix.x4 from swizzled WH (raw fp16 weights) ----
    uint4 aw[2][4];
#pragma unroll
    for (int m = 0; m < 2; m++) {
        const int row = cw * 32 + m * 16 + (lane & 15);
        const uint32_t rowbase =
            (uint32_t)__cvta_generic_to_shared(WH + row * 128);
        const int rx = row & 7;
#pragma unroll
        for (int kb = 0; kb < 4; kb++) {
            const int phys = (kb * 2 + (lane >> 4)) ^ rx;
            const uint32_t a = rowbase + phys * 16;
            asm volatile(
                "ldmatrix.sync.aligned.m8n8.x4.shared.b16 {%0,%1,%2,%3}, [%4];"
                : "=r"(aw[m][kb].x), "=r"(aw[m][kb].y),
                  "=r"(aw[m][kb].z), "=r"(aw[m][kb].w)
                : "r"(a));
        }
    }

    float acc[2][8][4];
#pragma unroll
    for (int m = 0; m < 2; m++)
#pragma unroll
        for (int nt = 0; nt < 8; nt++)
#pragma unroll
            for (int j = 0; j < 4; j++) acc[m][nt][j] = 0.0f;

    // ---- mainloop: 4 k-blocks x 8 n-tiles x 2 m-tiles of m16n8k16 (R4 exact) ----
#pragma unroll
    for (int kb = 0; kb < 4; kb++) {
#pragma unroll
        for (int nt = 0; nt < 8; nt++) {
            const uint2 bb = SB[(kb * 4 + t) * S2U + pixb + nt * 8 + g];
            asm volatile(
                "mma.sync.aligned.m16n8k16.row.col.f32.f16.f16.f32 "
                "{%0,%1,%2,%3}, {%4,%5,%6,%7}, {%8,%9}, {%0,%1,%2,%3};"
                : "+f"(acc[0][nt][0]), "+f"(acc[0][nt][1]),
                  "+f"(acc[0][nt][2]), "+f"(acc[0][nt][3])
                : "r"(aw[0][kb].x), "r"(aw[0][kb].y),
                  "r"(aw[0][kb].z), "r"(aw[0][kb].w),
                  "r"(bb.x), "r"(bb.y));
            asm volatile(
                "mma.sync.aligned.m16n8k16.row.col.f32.f16.f16.f32 "
                "{%0,%1,%2,%3}, {%4,%5,%6,%7}, {%8,%9}, {%0,%1,%2,%3};"
                : "+f"(acc[1][nt][0]), "+f"(acc[1][nt][1]),
                  "+f"(acc[1][nt][2]), "+f"(acc[1][nt][3])
                : "r"(aw[1][kb].x), "r"(aw[1][kb].y),
                  "r"(aw[1][kb].z), "r"(aw[1][kb].w),
                  "r"(bb.x), "r"(bb.y));
        }
    }

    __syncthreads();   // mainloop SB reads + WH consumed before union overwrite

    // ---- epilogue pt1: demodulate (acc*dcoef) + bias + clamp, STS [cout][pix] ----
#pragma unroll
    for (int m = 0; m < 2; m++) {
        const int row0 = cw * 32 + m * 16 + g;
        const float d0  = sdc[row0];
        const float d1  = sdc[row0 + 8];
        const float bv0 = __ldg(bias + row0);
        const float bv1 = __ldg(bias + row0 + 8);
#pragma unroll
        for (int nt = 0; nt < 8; nt++) {
            const int col = pixb + nt * 8 + t * 2;
            float2 v0, v1;
            v0.x = fminf(fmaxf(fmaf(acc[m][nt][0], d0, bv0), -256.0f), 256.0f);
            v0.y = fminf(fmaxf(fmaf(acc[m][nt][1], d0, bv0), -256.0f), 256.0f);
            v1.x = fminf(fmaxf(fmaf(acc[m][nt][2], d1, bv1), -256.0f), 256.0f);
            v1.y = fminf(fmaxf(fmaf(acc[m][nt][3], d1, bv1), -256.0f), 256.0f);
            *(float2*)&SE[row0 * SEF + col]       = v0;
            *(float2*)&SE[(row0 + 8) * SEF + col] = v1;
        }
    }
    __syncthreads();

    // ---- epilogue pt2: coalesced 512B-per-warp copy out (R4 exact) ----
    float* ob = out + ((size_t)b << 22) + hw0;
#pragma unroll
    for (int p = 0; p < 16; p++) {
        const int row = p * 4 + wid;               // cout
        float4 v = *(const float4*)&SE[row * SEF + lane * 4];
        __stcs((float4*)(ob + ((size_t)row << 16) + lane * 4), v);
    }
}

// ---------------- launch: ONE kernel, no prep ----------------
extern "C" void kernel_launch(void* const* d_in, const int* in_sizes, int n_in,
                              void* d_out, int out_size) {
    const float* x    = (const float*)d_in[0];
    const float* w    = (const float*)d_in[1];
    const float* bias = (const float*)d_in[2];
    float* out = (float*)d_out;

    const int total_pix = 16 * HWSZ;
    const int nblocks = total_pix / PTILE;   // 8192
    conv_mma_kernel<<<nblocks, 128>>>(x, w, bias, out);
}

// round 17
// speedup vs baseline: 1.4621x; 1.0152x over previous
#include <cuda_runtime.h>
#include <cuda_fp16.h>
#include <cstdint>

// ConvDemodulated: out[b,o,hw] = clip( sum_i x[b,i,hw] * Wn[o,i] + bias[o], -256, 256 )
// R13 = R4's kernel (fastest measured: 79.5us, ~97% of realistic HBM ceiling)
// + RAW-weight trick: mma uses raw fp16 W, epilogue applies dcoef[o] via fmaf
// + prep kernel rebuilt latency-optimal: 512 threads, fully parallel,
//   zero syncs, ~1.5us (the old 64-thread serial prep WAS the 9us wall gap).

#define CIN   64
#define COUT  64
#define HWSZ  65536
#define PTILE 128      // pixels per CTA
#define S2U   132      // staging stride (uint2), mod 16 == 4 -> conflict-free LDS.64
#define SEF   136      // epilogue stride (floats)

// Pre-packed RAW fp16 A-fragments: [kb(4)][mt(4)][lane(32)] uint4 (8 halves).
__device__ uint4 g_wfrag16[4 * 4 * 32];
__device__ float g_dcoef[COUT];

__device__ __forceinline__ uint32_t pack_h2(float lo, float hi) {
    __half2 h = __floats2half2_rn(lo, hi);
    return *reinterpret_cast<uint32_t*>(&h);
}

// ---------------- prep: 512 threads, parallel, no syncs (~1.5us) ----------------
__global__ void __launch_bounds__(512)
prep_w_kernel(const float* __restrict__ w) {
    const int tid = threadIdx.x;          // 0..511

    // --- row norms: 8 lanes per row, 2x LDG.128 each, shfl-tree reduce ---
    {
        const int r = tid >> 3;           // row 0..63
        const int s = tid & 7;            // 8-float segment
        const float4 v0 = __ldg((const float4*)(w + r * CIN + s * 8));
        const float4 v1 = __ldg((const float4*)(w + r * CIN + s * 8) + 1);
        float ss = v0.x*v0.x + v0.y*v0.y + v0.z*v0.z + v0.w*v0.w
                 + v1.x*v1.x + v1.y*v1.y + v1.z*v1.z + v1.w*v1.w;
        ss += __shfl_xor_sync(0xFFFFFFFFu, ss, 1);
        ss += __shfl_xor_sync(0xFFFFFFFFu, ss, 2);
        ss += __shfl_xor_sync(0xFFFFFFFFu, ss, 4);
        if (s == 0) g_dcoef[r] = rsqrtf(ss + 1e-8f);
    }

    // --- pack RAW fragments: one uint4 per thread (512 fragments total) ---
    // A-frag (m16n8k16 row-major): r = mt*16 + lane/4, c = kb*16 + 2*(lane%4)
    {
        const int e = tid;
        const int lane = e & 31, mt = (e >> 5) & 3, kb = e >> 7;
        const int r = mt * 16 + (lane >> 2);
        const int c = kb * 16 + 2 * (lane & 3);
        const float2 p0 = __ldg((const float2*)(w + r * CIN + c));
        const float2 p1 = __ldg((const float2*)(w + (r + 8) * CIN + c));
        const float2 p2 = __ldg((const float2*)(w + r * CIN + c + 8));
        const float2 p3 = __ldg((const float2*)(w + (r + 8) * CIN + c + 8));
        uint4 v;
        v.x = pack_h2(p0.x, p0.y);
        v.y = pack_h2(p1.x, p1.y);
        v.z = pack_h2(p2.x, p2.y);
        v.w = pack_h2(p3.x, p3.y);
        g_wfrag16[e] = v;
    }
}

// ---------------- main kernel (R4 exact + epilogue demod) ----------------
__global__ void __launch_bounds__(128, 4)
conv_mma_kernel(const float* __restrict__ x, const float* __restrict__ bias,
                float* __restrict__ out) {
    // Union: staging (16 quad-rows x 132 uint2 = 16.9KB) then epilogue (64 x 136 fp32)
    __shared__ __align__(16) float SE[COUT * SEF];
    uint2* SB = (uint2*)SE;

    const int tid  = threadIdx.x;
    const int lane = tid & 31;
    const int wid  = tid >> 5;     // 0..3
    const int cw   = wid & 1;      // cout half
    const int ph   = wid >> 1;     // pixel half
    const int t    = lane & 3;
    const int g    = lane >> 2;
    const int pixb = ph * 64;

    const int pixglob = blockIdx.x * PTILE;
    const int b   = pixglob >> 16;
    const int hw0 = pixglob & (HWSZ - 1);
    const float* xb = x + ((size_t)b << 22) + hw0;

    // ---- stage X: 16 front-batched LDG.128 hit DRAM immediately (R4 exact) ----
#pragma unroll
    for (int it = 0; it < 4; it++) {
        const int q  = it * 4 + wid;                 // 0..15
        const int k0 = it * 16 + wid * 2;
        const float* rp = xb + ((size_t)k0 << 16) + lane * 4;
        float4 va = __ldcs((const float4*)rp);
        float4 vb = __ldcs((const float4*)(rp + (1 << 16)));
        float4 vc = __ldcs((const float4*)(rp + (8 << 16)));
        float4 vd = __ldcs((const float4*)(rp + (9 << 16)));
        uint4 o0, o1;
        o0.x = pack_h2(va.x, vb.x); o0.y = pack_h2(vc.x, vd.x);
        o0.z = pack_h2(va.y, vb.y); o0.w = pack_h2(vc.y, vd.y);
        o1.x = pack_h2(va.z, vb.z); o1.y = pack_h2(vc.z, vd.z);
        o1.z = pack_h2(va.w, vb.w); o1.w = pack_h2(vc.w, vd.w);
        *(uint4*)&SB[q * S2U + lane * 4]     = o0;
        *(uint4*)&SB[q * S2U + lane * 4 + 2] = o1;
    }

    // ---- RAW A-fragments (all 4 k-blocks x 2 m-tiles), L1-hot pre-packed ----
    uint4 aw[2][4];
#pragma unroll
    for (int m = 0; m < 2; m++)
#pragma unroll
        for (int kb = 0; kb < 4; kb++)
            aw[m][kb] = __ldg(&g_wfrag16[(kb * 4 + cw * 2 + m) * 32 + lane]);

    float acc[2][8][4];
#pragma unroll
    for (int m = 0; m < 2; m++)
#pragma unroll
        for (int nt = 0; nt < 8; nt++)
#pragma unroll
            for (int j = 0; j < 4; j++) acc[m][nt][j] = 0.0f;

    __syncthreads();

    // ---- mainloop: 4 k-blocks x 8 n-tiles x 2 m-tiles of m16n8k16 (R4 exact) ----
#pragma unroll
    for (int kb = 0; kb < 4; kb++) {
#pragma unroll
        for (int nt = 0; nt < 8; nt++) {
            const uint2 bb = SB[(kb * 4 + t) * S2U + pixb + nt * 8 + g];
            asm volatile(
                "mma.sync.aligned.m16n8k16.row.col.f32.f16.f16.f32 "
                "{%0,%1,%2,%3}, {%4,%5,%6,%7}, {%8,%9}, {%0,%1,%2,%3};"
                : "+f"(acc[0][nt][0]), "+f"(acc[0][nt][1]),
                  "+f"(acc[0][nt][2]), "+f"(acc[0][nt][3])
                : "r"(aw[0][kb].x), "r"(aw[0][kb].y),
                  "r"(aw[0][kb].z), "r"(aw[0][kb].w),
                  "r"(bb.x), "r"(bb.y));
            asm volatile(
                "mma.sync.aligned.m16n8k16.row.col.f32.f16.f16.f32 "
                "{%0,%1,%2,%3}, {%4,%5,%6,%7}, {%8,%9}, {%0,%1,%2,%3};"
                : "+f"(acc[1][nt][0]), "+f"(acc[1][nt][1]),
                  "+f"(acc[1][nt][2]), "+f"(acc[1][nt][3])
                : "r"(aw[1][kb].x), "r"(aw[1][kb].y),
                  "r"(aw[1][kb].z), "r"(aw[1][kb].w),
                  "r"(bb.x), "r"(bb.y));
        }
    }

    __syncthreads();   // mainloop smem reads done before union overwrite

    // ---- epilogue pt1: demodulate (fmaf acc*dcoef + bias), clamp, STS ----
#pragma unroll
    for (int m = 0; m < 2; m++) {
        const int row0 = cw * 32 + m * 16 + g;
        const float d0  = __ldg(g_dcoef + row0);
        const float d1  = __ldg(g_dcoef + row0 + 8);
        const float bv0 = __ldg(bias + row0);
        const float bv1 = __ldg(bias + row0 + 8);
#pragma unroll
        for (int nt = 0; nt < 8; nt++) {
            const int col = pixb + nt * 8 + t * 2;
            float2 v0, v1;
            v0.x = fminf(fmaxf(fmaf(acc[m][nt][0], d0, bv0), -256.0f), 256.0f);
            v0.y = fminf(fmaxf(fmaf(acc[m][nt][1], d0, bv0), -256.0f), 256.0f);
            v1.x = fminf(fmaxf(fmaf(acc[m][nt][2], d1, bv1), -256.0f), 256.0f);
            v1.y = fminf(fmaxf(fmaf(acc[m][nt][3], d1, bv1), -256.0f), 256.0f);
            *(float2*)&SE[row0 * SEF + col]       = v0;
            *(float2*)&SE[(row0 + 8) * SEF + col] = v1;
        }
    }
    __syncthreads();

    // ---- epilogue pt2: coalesced 512B-per-warp copy out (R4 exact) ----
    float* ob = out + ((size_t)b << 22) + hw0;
#pragma unroll
    for (int p = 0; p < 16; p++) {
        const int row = p * 4 + wid;               // cout
        float4 v = *(const float4*)&SE[row * SEF + lane * 4];
        __stcs((float4*)(ob + ((size_t)row << 16) + lane * 4), v);
    }
}

// ---------------- launch ----------------
extern "C" void kernel_launch(void* const* d_in, const int* in_sizes, int n_in,
                              void* d_out, int out_size) {
    const float* x    = (const float*)d_in[0];
    const float* w    = (const float*)d_in[1];
    const float* bias = (const float*)d_in[2];
    float* out = (float*)d_out;

    prep_w_kernel<<<1, 512>>>(w);

    const int total_pix = 16 * HWSZ;
    const int nblocks = total_pix / PTILE;   // 8192
    conv_mma_kernel<<<nblocks, 128>>>(x, bias, out);
}